// round 4
// baseline (speedup 1.0000x reference)
#include <cuda_runtime.h>
#include <stdint.h>

// Morton encode: out[b,c, morton(i,j)] = x[b,c,i,j], N=256.
// morton bit layout: bit0=j0, bit1=i0, bit2=j1, bit3=i1, ...
// Gather form: out[m] = x[i(m), j(m)], j = even bits of m, i = odd bits.
//
// Each thread handles 8 consecutive outputs m..m+7 (m % 8 == 0):
//   j % 4 == 0, i % 2 == 0, and the 8 outputs are the 2x4 block
//   rows {i, i+1} x cols {j..j+3} in the interleaved order
//   (i,j),(i,j+1),(i+1,j),(i+1,j+1),(i,j+2),(i,j+3),(i+1,j+2),(i+1,j+3).
// => two aligned float4 loads, register shuffle, two contiguous float4 stores.
// Warp-level: loads hit 8 rows x 64B contiguous (all sectors full),
// stores are 1 KiB contiguous. Pure HBM-bound, ~256 MiB traffic.

static __global__ void __launch_bounds__(256)
morton_gather_8(const float4* __restrict__ in, float4* __restrict__ out,
                unsigned ngroups) {
    unsigned stride = gridDim.x * blockDim.x;
    for (unsigned g = blockIdx.x * blockDim.x + threadIdx.x; g < ngroups;
         g += stride) {
        unsigned plane = g >> 13;             // 8192 groups of 8 per 256x256 plane
        unsigned m = (g & 8191u) << 3;        // output element index in plane

        // Deinterleave: j = even bits, i = odd bits (8 bits each).
        unsigned j = m & 0x5555u;
        j = (j | (j >> 1)) & 0x3333u;
        j = (j | (j >> 2)) & 0x0F0Fu;
        j = (j | (j >> 4)) & 0x00FFu;         // multiple of 4

        unsigned i = (m >> 1) & 0x5555u;
        i = (i | (i >> 1)) & 0x3333u;
        i = (i | (i >> 2)) & 0x0F0Fu;
        i = (i | (i >> 4)) & 0x00FFu;         // even

        // float4 index of x[i, j] within full tensor
        unsigned src = (plane << 14) + (i << 6) + (j >> 2);
        float4 a = in[src];        // row i,   cols j..j+3
        float4 b = in[src + 64];   // row i+1, cols j..j+3 (256 floats = 64 float4)

        float4 o0 = make_float4(a.x, a.y, b.x, b.y);
        float4 o1 = make_float4(a.z, a.w, b.z, b.w);

        unsigned dst = g << 1;     // two float4 per group
        out[dst]     = o0;
        out[dst + 1] = o1;
    }
}

extern "C" void kernel_launch(void* const* d_in, const int* in_sizes, int n_in,
                              void* d_out, int out_size) {
    const float4* in = (const float4*)d_in[0];
    float4* out = (float4*)d_out;

    unsigned ngroups = (unsigned)(out_size >> 3);  // 1,048,576 for bench shape
    const int threads = 256;
    unsigned blocks = (ngroups + threads - 1) / threads;

    morton_gather_8<<<blocks, threads>>>(in, out, ngroups);
}